// round 1
// baseline (speedup 1.0000x reference)
#include <cuda_runtime.h>

#define NN   100000
#define EE   1600000
#define KDIM 128
#define ODIM 128      // H*D = 4*32
#define ALPHA 0.2f

// -------- device scratch (no allocations allowed) --------
__device__ float    g_ft[(size_t)NN * ODIM];   // 51.2 MB
__device__ float    g_al[NN];
__device__ float    g_ar[NN];
__device__ unsigned g_emax[NN];                // monotone-uint-encoded float max
__device__ float    g_denom[NN];
__device__ float    g_e[EE];
__device__ float    g_ex[EE];

// monotone float<->uint mapping for atomicMax on floats
__device__ __forceinline__ unsigned fenc(float f) {
    unsigned u = __float_as_uint(f);
    return (u & 0x80000000u) ? ~u : (u | 0x80000000u);
}
__device__ __forceinline__ float fdec(unsigned u) {
    return (u & 0x80000000u) ? __uint_as_float(u & 0x7fffffffu)
                             : __uint_as_float(~u);
}

// -------- K0: zero out + reset per-node reductions (graph-replay safe) ------
__global__ void k_init(float* __restrict__ out) {
    int i = blockIdx.x * blockDim.x + threadIdx.x;
    int stride = gridDim.x * blockDim.x;
    float4 z = make_float4(0.f, 0.f, 0.f, 0.f);
    const int n4 = NN * ODIM / 4;
    for (int j = i; j < n4; j += stride) ((float4*)out)[j] = z;
    for (int j = i; j < NN; j += stride) { g_emax[j] = 0u; g_denom[j] = 0.f; }
}

// -------- K1: ft = X @ W  (64-row tile, 256 threads, 48KB smem) -------------
__global__ __launch_bounds__(256)
void k_gemm(const float* __restrict__ A, const float* __restrict__ W) {
    __shared__ float As[64 * 64];    // 16 KB
    __shared__ float Bs[64 * 128];   // 32 KB
    const int tid = threadIdx.x;
    const int tx = tid & 31;     // 32 col-groups of 4
    const int ty = tid >> 5;     // 8 row-groups of 8
    const int row0 = blockIdx.x * 64;

    float acc[8][4];
#pragma unroll
    for (int r = 0; r < 8; r++)
#pragma unroll
        for (int j = 0; j < 4; j++) acc[r][j] = 0.f;

    for (int kt = 0; kt < 2; kt++) {
        // load A tile 64x64
#pragma unroll
        for (int p = 0; p < 4; p++) {
            int i = tid + p * 256;
            int r = i >> 4, c4 = i & 15;
            int grow = row0 + r;
            float4 v = make_float4(0.f, 0.f, 0.f, 0.f);
            if (grow < NN)
                v = *(const float4*)(A + (size_t)grow * KDIM + kt * 64 + c4 * 4);
            *(float4*)(As + r * 64 + c4 * 4) = v;
        }
        // load W tile 64x128
#pragma unroll
        for (int p = 0; p < 8; p++) {
            int i = tid + p * 256;
            int r = i >> 5, c4 = i & 31;
            *(float4*)(Bs + r * 128 + c4 * 4) =
                *(const float4*)(W + (size_t)(kt * 64 + r) * ODIM + c4 * 4);
        }
        __syncthreads();
#pragma unroll 8
        for (int k = 0; k < 64; k++) {
            float4 b = *(float4*)(Bs + k * 128 + tx * 4);
#pragma unroll
            for (int r = 0; r < 8; r++) {
                float a = As[(ty * 8 + r) * 64 + k];   // warp-uniform broadcast
                acc[r][0] += a * b.x;
                acc[r][1] += a * b.y;
                acc[r][2] += a * b.z;
                acc[r][3] += a * b.w;
            }
        }
        __syncthreads();
    }
#pragma unroll
    for (int r = 0; r < 8; r++) {
        int grow = row0 + ty * 8 + r;
        if (grow < NN) {
            float4 v = make_float4(acc[r][0], acc[r][1], acc[r][2], acc[r][3]);
            *(float4*)(g_ft + (size_t)grow * ODIM + tx * 4) = v;
        }
    }
}

// -------- K2: head-0 attention scores per node (warp per node) --------------
__global__ void k_scores(const float* __restrict__ attn_l,
                         const float* __restrict__ attn_r) {
    int node = blockIdx.x * 4 + (threadIdx.x >> 5);
    int lane = threadIdx.x & 31;
    if (node >= NN) return;
    float v  = g_ft[(size_t)node * ODIM + lane];   // head 0 = cols 0..31
    float sl = v * attn_l[lane];
    float sr = v * attn_r[lane];
#pragma unroll
    for (int o = 16; o; o >>= 1) {
        sl += __shfl_down_sync(0xffffffffu, sl, o);
        sr += __shfl_down_sync(0xffffffffu, sr, o);
    }
    if (lane == 0) { g_al[node] = sl; g_ar[node] = sr; }
}

// -------- K3: edge logits + segment max ------------------------------------
__global__ void k_edge1(const int* __restrict__ src, const int* __restrict__ dst) {
    int i = blockIdx.x * blockDim.x + threadIdx.x;
    if (i >= EE) return;
    int d = dst[i];
    float e = g_al[src[i]] + g_ar[d];
    e = (e > 0.f) ? e : ALPHA * e;
    g_e[i] = e;
    atomicMax(&g_emax[d], fenc(e));
}

// -------- K4: exp + segment sum --------------------------------------------
__global__ void k_edge2(const int* __restrict__ dst) {
    int i = blockIdx.x * blockDim.x + threadIdx.x;
    if (i >= EE) return;
    int d = dst[i];
    float m  = fdec(g_emax[d]);
    float ex = __expf(g_e[i] - m);
    g_ex[i] = ex;
    atomicAdd(&g_denom[d], ex);
}

// -------- K5: aggregation out[dst] += a * ft[src], warp per edge ------------
__global__ __launch_bounds__(256)
void k_agg(const int* __restrict__ src, const int* __restrict__ dst,
           float* __restrict__ out) {
    int e    = blockIdx.x * 8 + (threadIdx.x >> 5);
    int lane = threadIdx.x & 31;
    if (e >= EE) return;
    int s = 0, d = 0;
    float c = 0.f;
    if (lane == 0) {
        s = src[e];
        d = dst[e];
        c = g_ex[e] / g_denom[d];
    }
    s = __shfl_sync(0xffffffffu, s, 0);
    d = __shfl_sync(0xffffffffu, d, 0);
    c = __shfl_sync(0xffffffffu, c, 0);

    float4 v = *(const float4*)(g_ft + (size_t)s * ODIM + lane * 4);
    float* p = out + (size_t)d * ODIM + lane * 4;
    // sm_90+ vector reduction: one RED.128 instead of 4 scalar atomics
    asm volatile("red.global.add.v4.f32 [%0], {%1, %2, %3, %4};"
                 :: "l"(p), "f"(v.x * c), "f"(v.y * c), "f"(v.z * c), "f"(v.w * c)
                 : "memory");
}

// ---------------------------------------------------------------------------
extern "C" void kernel_launch(void* const* d_in, const int* in_sizes, int n_in,
                              void* d_out, int out_size) {
    const float* inputs = (const float*)d_in[0];
    const int*   src    = (const int*)d_in[1];
    const int*   dst    = (const int*)d_in[2];
    const float* fc_w   = (const float*)d_in[3];
    const float* attn_l = (const float*)d_in[4];
    const float* attn_r = (const float*)d_in[5];
    float* out = (float*)d_out;

    k_init  <<<2048, 256>>>(out);
    k_gemm  <<<(NN + 63) / 64, 256>>>(inputs, fc_w);
    k_scores<<<(NN + 3) / 4, 128>>>(attn_l, attn_r);
    k_edge1 <<<(EE + 255) / 256, 256>>>(src, dst);
    k_edge2 <<<(EE + 255) / 256, 256>>>(dst);
    k_agg   <<<EE / 8, 256>>>(src, dst, out);
}

// round 2
// speedup vs baseline: 1.6009x; 1.6009x over previous
#include <cuda_runtime.h>

#define NN   100000
#define EE   1600000
#define KDIM 128
#define ODIM 128      // H*D = 4*32
#define ALPHA 0.2f
#define NBLK_SCAN ((NN + 1023) / 1024)   // 98

// -------- device scratch (no allocations allowed) --------
__device__ float g_ft[(size_t)NN * ODIM];   // 51.2 MB
__device__ float g_al[NN];
__device__ float g_ar[NN];
__device__ float g_denom[NN];
__device__ int   g_cnt[NN];
__device__ int   g_off[NN];
__device__ int   g_cur[NN];
__device__ int   g_bsum[128];
__device__ int   g_ssrc[EE];                // src sorted by dst
__device__ float g_sex[EE];                 // exp(e) sorted by dst

// -------- K0: reset per-node reductions (graph-replay safe) -----------------
__global__ void k_init() {
    int i = blockIdx.x * blockDim.x + threadIdx.x;
    int stride = gridDim.x * blockDim.x;
    for (int j = i; j < NN; j += stride) { g_cnt[j] = 0; g_denom[j] = 0.f; }
}

// -------- K1: ft = X @ W  (64-row tile, 256 threads, 48KB smem) -------------
__global__ __launch_bounds__(256)
void k_gemm(const float* __restrict__ A, const float* __restrict__ W) {
    __shared__ float As[64 * 64];    // 16 KB
    __shared__ float Bs[64 * 128];   // 32 KB
    const int tid = threadIdx.x;
    const int tx = tid & 31;     // 32 col-groups of 4
    const int ty = tid >> 5;     // 8 row-groups of 8
    const int row0 = blockIdx.x * 64;

    float acc[8][4];
#pragma unroll
    for (int r = 0; r < 8; r++)
#pragma unroll
        for (int j = 0; j < 4; j++) acc[r][j] = 0.f;

    for (int kt = 0; kt < 2; kt++) {
#pragma unroll
        for (int p = 0; p < 4; p++) {
            int i = tid + p * 256;
            int r = i >> 4, c4 = i & 15;
            int grow = row0 + r;
            float4 v = make_float4(0.f, 0.f, 0.f, 0.f);
            if (grow < NN)
                v = *(const float4*)(A + (size_t)grow * KDIM + kt * 64 + c4 * 4);
            *(float4*)(As + r * 64 + c4 * 4) = v;
        }
#pragma unroll
        for (int p = 0; p < 8; p++) {
            int i = tid + p * 256;
            int r = i >> 5, c4 = i & 31;
            *(float4*)(Bs + r * 128 + c4 * 4) =
                *(const float4*)(W + (size_t)(kt * 64 + r) * ODIM + c4 * 4);
        }
        __syncthreads();
#pragma unroll 8
        for (int k = 0; k < 64; k++) {
            float4 b = *(float4*)(Bs + k * 128 + tx * 4);
#pragma unroll
            for (int r = 0; r < 8; r++) {
                float a = As[(ty * 8 + r) * 64 + k];
                acc[r][0] += a * b.x;
                acc[r][1] += a * b.y;
                acc[r][2] += a * b.z;
                acc[r][3] += a * b.w;
            }
        }
        __syncthreads();
    }
#pragma unroll
    for (int r = 0; r < 8; r++) {
        int grow = row0 + ty * 8 + r;
        if (grow < NN) {
            float4 v = make_float4(acc[r][0], acc[r][1], acc[r][2], acc[r][3]);
            *(float4*)(g_ft + (size_t)grow * ODIM + tx * 4) = v;
        }
    }
}

// -------- K2: head-0 attention scores per node (warp per node) --------------
__global__ void k_scores(const float* __restrict__ attn_l,
                         const float* __restrict__ attn_r) {
    int node = blockIdx.x * 8 + (threadIdx.x >> 5);
    int lane = threadIdx.x & 31;
    if (node >= NN) return;
    float v  = g_ft[(size_t)node * ODIM + lane];   // head 0 = cols 0..31
    float sl = v * attn_l[lane];
    float sr = v * attn_r[lane];
#pragma unroll
    for (int o = 16; o; o >>= 1) {
        sl += __shfl_down_sync(0xffffffffu, sl, o);
        sr += __shfl_down_sync(0xffffffffu, sr, o);
    }
    if (lane == 0) { g_al[node] = sl; g_ar[node] = sr; }
}

// -------- K3: histogram of dst ---------------------------------------------
__global__ void k_hist(const int* __restrict__ dst) {
    int i = blockIdx.x * blockDim.x + threadIdx.x;
    if (i < EE) atomicAdd(&g_cnt[dst[i]], 1);
}

// -------- K4a: per-block exclusive scan of counts --------------------------
__global__ __launch_bounds__(1024)
void k_scan1() {
    __shared__ int sh[1024];
    int tid = threadIdx.x;
    int i = blockIdx.x * 1024 + tid;
    int v = (i < NN) ? g_cnt[i] : 0;
    sh[tid] = v;
    __syncthreads();
#pragma unroll
    for (int o = 1; o < 1024; o <<= 1) {
        int t = (tid >= o) ? sh[tid - o] : 0;
        __syncthreads();
        sh[tid] += t;
        __syncthreads();
    }
    if (i < NN) g_off[i] = sh[tid] - v;          // exclusive
    if (tid == 1023) g_bsum[blockIdx.x] = sh[1023];
}

// -------- K4b: serial scan of 98 block sums (tiny) -------------------------
__global__ void k_scan2() {
    if (threadIdx.x == 0 && blockIdx.x == 0) {
        int run = 0;
        for (int b = 0; b < NBLK_SCAN; b++) {
            int t = g_bsum[b];
            g_bsum[b] = run;
            run += t;
        }
    }
}

// -------- K4c: add block offsets + init scatter cursors --------------------
__global__ void k_scan3() {
    int i = blockIdx.x * blockDim.x + threadIdx.x;
    if (i < NN) {
        int o = g_off[i] + g_bsum[i >> 10];
        g_off[i] = o;
        g_cur[i] = o;
    }
}

// -------- K5: fused edge pass: logits, exp, denom, scatter-sort ------------
__global__ void k_edge(const int* __restrict__ src, const int* __restrict__ dst) {
    int i = blockIdx.x * blockDim.x + threadIdx.x;
    if (i >= EE) return;
    int s = src[i];
    int d = dst[i];
    float e = g_al[s] + g_ar[d];
    e = (e > 0.f) ? e : ALPHA * e;
    float ex = __expf(e);           // |e| <~ 10: safe without max-shift
    atomicAdd(&g_denom[d], ex);
    int pos = atomicAdd(&g_cur[d], 1);
    g_ssrc[pos] = s;
    g_sex[pos]  = ex;
}

// -------- K6: aggregation, warp per dst node (no atomics) ------------------
__global__ __launch_bounds__(256)
void k_agg(float* __restrict__ out) {
    int node = blockIdx.x * 8 + (threadIdx.x >> 5);
    int lane = threadIdx.x & 31;
    if (node >= NN) return;
    int beg = g_off[node];
    int cnt = g_cnt[node];
    float inv = (cnt > 0) ? __frcp_rn(g_denom[node]) : 0.f;

    float4 acc = make_float4(0.f, 0.f, 0.f, 0.f);

    int   s_n  = 0;
    float ex_n = 0.f;
    if (cnt > 0) { s_n = g_ssrc[beg]; ex_n = g_sex[beg]; }
    for (int k = 0; k < cnt; k++) {
        int   s  = s_n;
        float c  = ex_n * inv;
        if (k + 1 < cnt) { s_n = g_ssrc[beg + k + 1]; ex_n = g_sex[beg + k + 1]; }
        float4 v = *(const float4*)(g_ft + ((size_t)s << 7) + (lane << 2));
        acc.x += c * v.x;
        acc.y += c * v.y;
        acc.z += c * v.z;
        acc.w += c * v.w;
    }
    *(float4*)(out + ((size_t)node << 7) + (lane << 2)) = acc;
}

// ---------------------------------------------------------------------------
extern "C" void kernel_launch(void* const* d_in, const int* in_sizes, int n_in,
                              void* d_out, int out_size) {
    const float* inputs = (const float*)d_in[0];
    const int*   src    = (const int*)d_in[1];
    const int*   dst    = (const int*)d_in[2];
    const float* fc_w   = (const float*)d_in[3];
    const float* attn_l = (const float*)d_in[4];
    const float* attn_r = (const float*)d_in[5];
    float* out = (float*)d_out;

    k_init  <<<512, 256>>>();
    k_gemm  <<<(NN + 63) / 64, 256>>>(inputs, fc_w);
    k_scores<<<(NN + 7) / 8, 256>>>(attn_l, attn_r);
    k_hist  <<<(EE + 255) / 256, 256>>>(dst);
    k_scan1 <<<NBLK_SCAN, 1024>>>();
    k_scan2 <<<1, 32>>>();
    k_scan3 <<<(NN + 255) / 256, 256>>>();
    k_edge  <<<(EE + 255) / 256, 256>>>(src, dst);
    k_agg   <<<(NN + 7) / 8, 256>>>(out);
}